// round 3
// baseline (speedup 1.0000x reference)
#include <cuda_runtime.h>

// ---------------------------------------------------------------------------
// ASDHead fused v2:
//   out[b,t,n] = sum_h relu(fproj[b,t,h] + sproj[b,n,h]) * w[h] + b_head
// K_prep (96 blocks): transpose W_f -> g_Wt  +  sproj = slots@W_s + b_proj
// K_fused (256 blocks, 32-t tiles, 2 blocks/SM): register GEMM (FFMA2,
//   k-pair packed) -> skewed shared f-tile -> relu-dot, s/w in regs, shfl
//   reduce. Register budget held under 128 for 2-block residency.
// ---------------------------------------------------------------------------

#define D_MODEL 256
#define D_HID   128
#define BATCH   8
#define SEQ     1024
#define NSLOT   64

typedef unsigned long long u64;

__device__ float g_sproj[BATCH * NSLOT * D_HID];  // 256 KB
__device__ float g_Wt[D_HID * D_MODEL];           // W_f^T [h][k], 128 KB

// -------------------- f32x2 helpers ----------------------------------------
__device__ __forceinline__ u64 fma2(u64 a, u64 b, u64 c) {
    u64 d;
    asm("fma.rn.f32x2 %0, %1, %2, %3;" : "=l"(d) : "l"(a), "l"(b), "l"(c));
    return d;
}
__device__ __forceinline__ u64 add2(u64 a, u64 b) {
    u64 d;
    asm("add.rn.f32x2 %0, %1, %2;" : "=l"(d) : "l"(a), "l"(b));
    return d;
}
__device__ __forceinline__ u64 pack2(float lo, float hi) {
    u64 r;
    asm("mov.b64 %0, {%1, %2};" : "=l"(r) : "f"(lo), "f"(hi));
    return r;
}
__device__ __forceinline__ void unpack2(u64 v, float& lo, float& hi) {
    asm("mov.b64 {%0, %1}, %2;" : "=f"(lo), "=f"(hi) : "l"(v));
}

union F4U2 {
    float4 f4;
    struct { u64 a, b; } u;
};

// -------------------- K_prep: sproj (blocks 0..63) + transpose (64..95) ----
__global__ void __launch_bounds__(256) k_prep(const float* __restrict__ slots,
                                              const float* __restrict__ Wproj,
                                              const float* __restrict__ bproj) {
    int tid = threadIdx.x;
    if (blockIdx.x < 64) {
        // ---- sproj: 8 slot rows per block, W_s streamed once per block ----
        __shared__ float ssh[8][D_MODEL];
        int b = blockIdx.x >> 3, ng = blockIdx.x & 7;
#pragma unroll
        for (int i = 0; i < 2; i++) {
            int q = i * 256 + tid;
            int row = q >> 6, c4 = q & 63;
            *(float4*)&ssh[row][c4 * 4] =
                *(const float4*)(slots + (b * NSLOT + ng * 8 + row) * D_MODEL + c4 * 4);
        }
        __syncthreads();
        int nl = tid >> 5, hq = tid & 31;
        const float* Ws = Wproj + D_MODEL * D_HID;
        float a0 = 0.f, a1 = 0.f, a2 = 0.f, a3 = 0.f;
#pragma unroll 8
        for (int k = 0; k < D_MODEL; k++) {
            float sv = ssh[nl][k];
            float4 wv = *(const float4*)(Ws + k * D_HID + hq * 4);
            a0 = fmaf(sv, wv.x, a0);
            a1 = fmaf(sv, wv.y, a1);
            a2 = fmaf(sv, wv.z, a2);
            a3 = fmaf(sv, wv.w, a3);
        }
        float4 bp = *(const float4*)(bproj + hq * 4);
        float4 o;
        o.x = a0 + bp.x; o.y = a1 + bp.y; o.z = a2 + bp.z; o.w = a3 + bp.w;
        *(float4*)(g_sproj + (b * NSLOT + ng * 8 + nl) * D_HID + hq * 4) = o;
    } else {
        // ---- tiled transpose: g_Wt[h][k] = W_proj[k][h] ----
        __shared__ float tile[32][33];
        int bid = blockIdx.x - 64;
        int k0 = (bid & 7) * 32, h0 = (bid >> 3) * 32;
        int r = tid >> 5, c = tid & 31;
#pragma unroll
        for (int i = 0; i < 4; i++) {
            int row = i * 8 + r;
            tile[row][c] = Wproj[(k0 + row) * D_HID + h0 + c];
        }
        __syncthreads();
#pragma unroll
        for (int i = 0; i < 4; i++) {
            int row = i * 8 + r;
            g_Wt[(h0 + row) * D_MODEL + k0 + c] = tile[c][row];
        }
    }
}

// -------------------- K_fused: GEMM + relu-dot, 32-t tiles -----------------
// grid 256: b = blk>>5, t0 = (blk&31)*32.  256 threads, 2 blocks/SM.
// Phase A: C[32,128] = A_tile @ W_f.  warp w owns rows 4w..4w+3; lane l owns
//   cols {l, l+32, l+64, l+96}.  FFMA2 halves accumulate even/odd k.
// Phase B: thread = (n = tid>>2, chunk = tid&3 owning 32 h); f via broadcast
//   LDS.128 from skewed fsh; shfl-xor reduce over the 4 chunk lanes.
#define AS_STRIDE 36
#define FS_STRIDE 144

__global__ void __launch_bounds__(256, 2) k_fused(const float* __restrict__ features,
                                                  const float* __restrict__ whead,
                                                  const float* __restrict__ bhead,
                                                  float* __restrict__ out) {
    __shared__ float As[32 * AS_STRIDE];    //  4.5 KB
    __shared__ float Bs[128 * AS_STRIDE];   // 18.0 KB
    __shared__ float fsh[32 * FS_STRIDE];   // 18.0 KB

    int tid = threadIdx.x, warp = tid >> 5, lane = tid & 31;
    int b = blockIdx.x >> 5, t0 = (blockIdx.x & 31) * 32;
    const float* A = features + (b * SEQ + t0) * D_MODEL;

    u64 acc[4][4];
#pragma unroll
    for (int i = 0; i < 4; i++)
#pragma unroll
        for (int j = 0; j < 4; j++) acc[i][j] = 0ULL;

    // ---------------- Phase A: GEMM -------------------------------------
#pragma unroll 1
    for (int kc = 0; kc < D_MODEL; kc += 32) {
        {   // A tile: 256 float4, one per thread
            int row = tid >> 3, c4 = (tid & 7) * 4;
            *(float4*)&As[row * AS_STRIDE + c4] =
                *(const float4*)(A + row * D_MODEL + kc + c4);
        }
#pragma unroll
        for (int i = 0; i < 4; i++) {   // B tile: 1024 float4
            int q = i * 256 + tid;
            int row = q >> 3, c4 = (q & 7) * 4;
            *(float4*)&Bs[row * AS_STRIDE + c4] =
                *(const float4*)(g_Wt + row * D_MODEL + kc + c4);
        }
        __syncthreads();

#pragma unroll
        for (int k4 = 0; k4 < 32; k4 += 4) {
            u64 a2[4][2], b2[4][2];
#pragma unroll
            for (int i = 0; i < 4; i++) {
                F4U2 t;
                t.f4 = *(const float4*)&As[(warp * 4 + i) * AS_STRIDE + k4];
                a2[i][0] = t.u.a; a2[i][1] = t.u.b;
            }
#pragma unroll
            for (int j = 0; j < 4; j++) {
                F4U2 t;
                t.f4 = *(const float4*)&Bs[(lane + 32 * j) * AS_STRIDE + k4];
                b2[j][0] = t.u.a; b2[j][1] = t.u.b;
            }
#pragma unroll
            for (int i = 0; i < 4; i++)
#pragma unroll
                for (int j = 0; j < 4; j++) {
                    acc[i][j] = fma2(a2[i][0], b2[j][0], acc[i][j]);
                    acc[i][j] = fma2(a2[i][1], b2[j][1], acc[i][j]);
                }
        }
        __syncthreads();
    }

    // ---------------- writeback f-tile to skewed shared ------------------
    // col n = lane + 32j -> skewed col 36j + lane (conflict-free STS.32)
#pragma unroll
    for (int i = 0; i < 4; i++)
#pragma unroll
        for (int j = 0; j < 4; j++) {
            float lo, hi;
            unpack2(acc[i][j], lo, hi);
            fsh[(warp * 4 + i) * FS_STRIDE + 36 * j + lane] = lo + hi;
        }

    // s/w into registers (acc is dead; keeps peak regs < 128)
    int n = tid >> 2, chunk = tid & 3;
    u64 s2[16], w2[16];
    {
        const float* sp = g_sproj + (b * NSLOT + n) * D_HID + chunk * 32;
        const float* wp = whead + chunk * 32;
#pragma unroll
        for (int i = 0; i < 8; i++) {
            F4U2 t;
            t.f4 = *(const float4*)(sp + i * 4);
            s2[2 * i] = t.u.a; s2[2 * i + 1] = t.u.b;
            t.f4 = *(const float4*)(wp + i * 4);
            w2[2 * i] = t.u.a; w2[2 * i + 1] = t.u.b;
        }
    }
    float bh = bhead[0];
    __syncthreads();

    // ---------------- Phase B: relu-dot ----------------------------------
    float* outp = out + (b * SEQ + t0) * NSLOT + n;
#pragma unroll 1
    for (int t = 0; t < 32; t++) {
        const float* fp = fsh + t * FS_STRIDE + chunk * 36;
        u64 f2[16];
#pragma unroll
        for (int i = 0; i < 8; i++) {
            F4U2 v;
            v.f4 = *(const float4*)(fp + i * 4);
            f2[2 * i] = v.u.a; f2[2 * i + 1] = v.u.b;
        }
        u64 acc0 = 0ULL, acc1 = 0ULL;
#pragma unroll
        for (int kk = 0; kk < 16; kk++) {
            u64 x = add2(f2[kk], s2[kk]);
            float lo, hi;
            unpack2(x, lo, hi);
            lo = fmaxf(lo, 0.f);   // FMNMX -> alu pipe, overlaps fma pipe
            hi = fmaxf(hi, 0.f);
            if (kk & 1) acc1 = fma2(pack2(lo, hi), w2[kk], acc1);
            else        acc0 = fma2(pack2(lo, hi), w2[kk], acc0);
        }
        u64 r = add2(acc0, acc1);
        r = add2(r, __shfl_xor_sync(0xffffffffu, r, 1));
        r = add2(r, __shfl_xor_sync(0xffffffffu, r, 2));
        if (chunk == 0) {
            float lo, hi;
            unpack2(r, lo, hi);
            outp[t * NSLOT] = lo + hi + bh;
        }
    }
}

// -------------------- launch -----------------------------------------------
extern "C" void kernel_launch(void* const* d_in, const int* in_sizes, int n_in,
                              void* d_out, int out_size) {
    const float* features = (const float*)d_in[0];  // (8,1024,256)
    const float* slots    = (const float*)d_in[1];  // (8,64,256)
    const float* W_proj   = (const float*)d_in[2];  // (512,128)
    const float* b_proj   = (const float*)d_in[3];  // (128)
    const float* w_head   = (const float*)d_in[4];  // (128)
    const float* b_head   = (const float*)d_in[5];  // (1)
    float* out = (float*)d_out;                     // (8,1024,64)

    k_prep<<<96, 256>>>(slots, W_proj, b_proj);
    k_fused<<<256, 256>>>(features, w_head, b_head, out);
}

// round 4
// speedup vs baseline: 1.1507x; 1.1507x over previous
#include <cuda_runtime.h>

// ---------------------------------------------------------------------------
// ASDHead fused v3 — wavefront-clean design:
//   out[b,t,n] = sum_h relu(fproj[b,t,h] + sproj[b,n,h]) * w[h] + b_head
// k_prep: transpose W_f -> g_Wt + sproj = slots@W_s + b_proj (96 blocks)
// k_fused (256 blocks, 32-t tiles): Phase A register GEMM (FFMA2, strided
//   row/col ownership -> all LDS 1 wavefront), Phase B h-streamed relu-dot
//   with 4t x 2n micro-tile. All shared strides bank-engineered.
// ---------------------------------------------------------------------------

#define D_MODEL 256
#define D_HID   128
#define BATCH   8
#define SEQ     1024
#define NSLOT   64

typedef unsigned long long u64;

__device__ float g_sproj[BATCH * NSLOT * D_HID];  // 256 KB
__device__ float g_Wt[D_HID * D_MODEL];           // W_f^T [h][k], 128 KB

// -------------------- f32x2 helpers ----------------------------------------
__device__ __forceinline__ u64 fma2(u64 a, u64 b, u64 c) {
    u64 d;
    asm("fma.rn.f32x2 %0, %1, %2, %3;" : "=l"(d) : "l"(a), "l"(b), "l"(c));
    return d;
}
__device__ __forceinline__ u64 add2(u64 a, u64 b) {
    u64 d;
    asm("add.rn.f32x2 %0, %1, %2;" : "=l"(d) : "l"(a), "l"(b));
    return d;
}
__device__ __forceinline__ void unpack2(u64 v, float& lo, float& hi) {
    asm("mov.b64 {%0, %1}, %2;" : "=f"(lo), "=f"(hi) : "l"(v));
}
__device__ __forceinline__ u64 relu2(u64 x) {
    float lo, hi;
    unpack2(x, lo, hi);
    lo = fmaxf(lo, 0.f);          // FMNMX on alu pipe
    hi = fmaxf(hi, 0.f);
    u64 r;
    asm("mov.b64 %0, {%1, %2};" : "=l"(r) : "f"(lo), "f"(hi));
    return r;
}

union F4U2 {
    float4 f4;
    struct { u64 a, b; } u;
};

// -------------------- K_prep: sproj (blocks 0..63) + transpose (64..95) ----
__global__ void __launch_bounds__(256) k_prep(const float* __restrict__ slots,
                                              const float* __restrict__ Wproj,
                                              const float* __restrict__ bproj) {
    int tid = threadIdx.x;
    if (blockIdx.x < 64) {
        __shared__ float ssh[8][D_MODEL];
        int b = blockIdx.x >> 3, ng = blockIdx.x & 7;
#pragma unroll
        for (int i = 0; i < 2; i++) {
            int q = i * 256 + tid;
            int row = q >> 6, c4 = q & 63;
            *(float4*)&ssh[row][c4 * 4] =
                *(const float4*)(slots + (b * NSLOT + ng * 8 + row) * D_MODEL + c4 * 4);
        }
        __syncthreads();
        int nl = tid >> 5, hq = tid & 31;
        const float* Ws = Wproj + D_MODEL * D_HID;
        float a0 = 0.f, a1 = 0.f, a2 = 0.f, a3 = 0.f;
#pragma unroll 8
        for (int k = 0; k < D_MODEL; k++) {
            float sv = ssh[nl][k];
            float4 wv = *(const float4*)(Ws + k * D_HID + hq * 4);
            a0 = fmaf(sv, wv.x, a0);
            a1 = fmaf(sv, wv.y, a1);
            a2 = fmaf(sv, wv.z, a2);
            a3 = fmaf(sv, wv.w, a3);
        }
        float4 bp = *(const float4*)(bproj + hq * 4);
        float4 o;
        o.x = a0 + bp.x; o.y = a1 + bp.y; o.z = a2 + bp.z; o.w = a3 + bp.w;
        *(float4*)(g_sproj + (b * NSLOT + ng * 8 + nl) * D_HID + hq * 4) = o;
    } else {
        __shared__ float tile[32][33];
        int bid = blockIdx.x - 64;
        int k0 = (bid & 7) * 32, h0 = (bid >> 3) * 32;
        int r = tid >> 5, c = tid & 31;
#pragma unroll
        for (int i = 0; i < 4; i++) {
            int row = i * 8 + r;
            tile[row][c] = Wproj[(k0 + row) * D_HID + h0 + c];
        }
        __syncthreads();
#pragma unroll
        for (int i = 0; i < 4; i++) {
            int row = i * 8 + r;
            g_Wt[(h0 + row) * D_MODEL + k0 + c] = tile[c][row];
        }
    }
}

// -------------------- K_fused ----------------------------------------------
// grid 256: b = blk>>5, t0 = (blk&31)*32.  256 threads, 2 blocks/SM.
//
// Shared layout (dynamic, 74240 B):
//   As  [32][36]   floats   @0      (tile of features)
//   Bs  [128][36]  floats   @1152   (tile of W_f^T)
//   fsh [32][132]  floats   @5760   (f_proj tile, scalar [t][h])
//   ssh [64][132]  floats   @9984   (s_proj for this b, scalar [n][h])
//   wsh [64]       u64      @18432  (w_head packed pairs)
#define AS_OFF  0
#define BS_OFF  1152
#define FSH_OFF 5760
#define SSH_OFF 9984
#define WSH_OFF 18432
#define SMEM_FLOATS (18432 + 128)

__global__ void __launch_bounds__(256, 2) k_fused(const float* __restrict__ features,
                                                  const float* __restrict__ whead,
                                                  const float* __restrict__ bhead,
                                                  float* __restrict__ out) {
    extern __shared__ float sm[];
    float* As  = sm + AS_OFF;
    float* Bs  = sm + BS_OFF;
    float* fsh = sm + FSH_OFF;
    float* ssh = sm + SSH_OFF;
    u64*   wsh = (u64*)(sm + WSH_OFF);

    int tid = threadIdx.x, warp = tid >> 5, lane = tid & 31;
    int b = blockIdx.x >> 5, t0 = (blockIdx.x & 31) * 32;
    const float* A = features + (b * SEQ + t0) * D_MODEL;

    // Phase A ownership: rows mq+8i (strided), cols warp*16 + nq + 4j (strided)
    int mq = lane & 7, nq = lane >> 3;

    u64 acc[4][4];
#pragma unroll
    for (int i = 0; i < 4; i++)
#pragma unroll
        for (int j = 0; j < 4; j++) acc[i][j] = 0ULL;

    // ---------------- Phase A: GEMM f = A @ W_f --------------------------
#pragma unroll 1
    for (int kc = 0; kc < D_MODEL; kc += 32) {
        {   // As: 256 float4, one per thread (coalesced LDG, STS.128)
            int row = tid >> 3, c4 = (tid & 7) * 4;
            *(float4*)&As[row * 36 + c4] =
                *(const float4*)(A + row * D_MODEL + kc + c4);
        }
#pragma unroll
        for (int i = 0; i < 4; i++) {   // Bs: 1024 float4
            int q = i * 256 + tid;
            int row = q >> 3, c4 = (q & 7) * 4;
            *(float4*)&Bs[row * 36 + c4] =
                *(const float4*)(g_Wt + row * D_MODEL + kc + c4);
        }
        __syncthreads();

#pragma unroll
        for (int k4 = 0; k4 < 32; k4 += 4) {
            u64 alo[4], ahi[4], blo[4], bhi[4];
#pragma unroll
            for (int i = 0; i < 4; i++) {        // 8 unique rows -> 1 wf
                F4U2 t;
                t.f4 = *(const float4*)&As[(mq + 8 * i) * 36 + k4];
                alo[i] = t.u.a; ahi[i] = t.u.b;
            }
#pragma unroll
            for (int j = 0; j < 4; j++) {        // 4 unique rows -> 1 wf
                F4U2 t;
                t.f4 = *(const float4*)&Bs[(warp * 16 + nq + 4 * j) * 36 + k4];
                blo[j] = t.u.a; bhi[j] = t.u.b;
            }
#pragma unroll
            for (int i = 0; i < 4; i++)
#pragma unroll
                for (int j = 0; j < 4; j++) {
                    acc[i][j] = fma2(alo[i], blo[j], acc[i][j]);
                    acc[i][j] = fma2(ahi[i], bhi[j], acc[i][j]);
                }
        }
        __syncthreads();
    }

    // ---------------- writeback f tile (conflict-free STS.32) ------------
#pragma unroll
    for (int i = 0; i < 4; i++)
#pragma unroll
        for (int j = 0; j < 4; j++) {
            float lo, hi;
            unpack2(acc[i][j], lo, hi);
            fsh[(mq + 8 * i) * 132 + warp * 16 + nq + 4 * j] = lo + hi;
        }

    // ---------------- stage s tile + w (straight copies) -----------------
#pragma unroll
    for (int i = 0; i < 8; i++) {
        int q = i * 256 + tid;
        int n = q >> 5, c4 = (q & 31) * 4;
        *(float4*)&ssh[n * 132 + c4] =
            *(const float4*)(g_sproj + (b * NSLOT + n) * D_HID + c4);
    }
    if (tid < 64) wsh[tid] = ((const u64*)whead)[tid];
    float bh = bhead[0];
    __syncthreads();

    // ---------------- Phase B: h-streamed relu-dot, 4t x 2n --------------
    int tq = lane >> 2, ng = lane & 3;
    int nn = warp * 8 + ng * 2;                 // thread's n pair {nn, nn+1}
    const float* fp = fsh + tq * 132;           // t = tq + 8i
    const float* sp = ssh + nn * 132;

    u64 bacc[4][2];
#pragma unroll
    for (int i = 0; i < 4; i++) { bacc[i][0] = 0ULL; bacc[i][1] = 0ULL; }

#pragma unroll 4
    for (int hp = 0; hp < 64; hp++) {
        u64 w2 = wsh[hp];                       // broadcast
        u64 f2[4], s2[2];
#pragma unroll
        for (int i = 0; i < 4; i++)             // 8 unique 8B -> 1 wf each
            f2[i] = *(const u64*)&fp[i * 8 * 132 + 2 * hp];
        s2[0] = *(const u64*)&sp[2 * hp];
        s2[1] = *(const u64*)&sp[132 + 2 * hp];
#pragma unroll
        for (int i = 0; i < 4; i++)
#pragma unroll
            for (int u = 0; u < 2; u++) {
                u64 x = relu2(add2(f2[i], s2[u]));
                bacc[i][u] = fma2(x, w2, bacc[i][u]);
            }
    }

    // ---------------- writeback (STG.64, 32B-contiguous per t-row) -------
#pragma unroll
    for (int i = 0; i < 4; i++) {
        int t = tq + 8 * i;
        float lo0, hi0, lo1, hi1;
        unpack2(bacc[i][0], lo0, hi0);
        unpack2(bacc[i][1], lo1, hi1);
        float2 o;
        o.x = lo0 + hi0 + bh;
        o.y = lo1 + hi1 + bh;
        *(float2*)&out[(b * SEQ + t0 + t) * NSLOT + nn] = o;
    }
}

// -------------------- launch -----------------------------------------------
extern "C" void kernel_launch(void* const* d_in, const int* in_sizes, int n_in,
                              void* d_out, int out_size) {
    const float* features = (const float*)d_in[0];  // (8,1024,256)
    const float* slots    = (const float*)d_in[1];  // (8,64,256)
    const float* W_proj   = (const float*)d_in[2];  // (512,128)
    const float* b_proj   = (const float*)d_in[3];  // (128)
    const float* w_head   = (const float*)d_in[4];  // (128)
    const float* b_head   = (const float*)d_in[5];  // (1)
    float* out = (float*)d_out;                     // (8,1024,64)

    cudaFuncSetAttribute(k_fused, cudaFuncAttributeMaxDynamicSharedMemorySize,
                         SMEM_FLOATS * 4);

    k_prep<<<96, 256>>>(slots, W_proj, b_proj);
    k_fused<<<256, 256, SMEM_FLOATS * 4>>>(features, w_head, b_head, out);
}

// round 9
// speedup vs baseline: 1.1687x; 1.0156x over previous
#include <cuda_runtime.h>
#include <cuda_bf16.h>
#include <cstdint>

// ---------------------------------------------------------------------------
// ASDHead v6.1 — legacy-HMMA tensor path (tcgen05 rejected: harness builds
// compute_103 PTX, arch-suffix features unavailable). Fix vs v6: B staging
// copied only half of each 32-bf16 slot (uninitialized smem fed the mma).
//  k_prep     : sproj = slots@W_s + b_proj (fp32)  +  W_f^T -> bf16 hi/lo
//  k_gemm_mma : f_proj = features @ W_f via mma.sync m16n8k16 bf16,
//               3-product hi/lo split, fp32 accum. A frags direct from GMEM,
//               B staged in padded smem. grid 256.
//  k_out      : out = sum_h relu(f+s)*w + b. 16-t tiles, grid 512.
// ---------------------------------------------------------------------------

#define D_MODEL 256
#define D_HID   128
#define BATCH   8
#define SEQ     1024
#define NSLOT   64
#define MROWS   (BATCH * SEQ)

typedef unsigned long long u64;
typedef unsigned int u32;

__device__ float g_sproj[BATCH * NSLOT * D_HID];                 // 256 KB
__device__ __align__(16) __nv_bfloat16 g_Whi[D_HID * D_MODEL];   // W^T hi [h][k]
__device__ __align__(16) __nv_bfloat16 g_Wlo[D_HID * D_MODEL];   // W^T lo [h][k]
__device__ float g_fproj[MROWS * D_HID];                         // 4 MB

// -------------------- helpers ----------------------------------------------
__device__ __forceinline__ u64 fma2(u64 a, u64 b, u64 c) {
    u64 d; asm("fma.rn.f32x2 %0, %1, %2, %3;" : "=l"(d) : "l"(a), "l"(b), "l"(c));
    return d;
}
__device__ __forceinline__ u64 add2(u64 a, u64 b) {
    u64 d; asm("add.rn.f32x2 %0, %1, %2;" : "=l"(d) : "l"(a), "l"(b));
    return d;
}
__device__ __forceinline__ void unpack2(u64 v, float& lo, float& hi) {
    asm("mov.b64 {%0, %1}, %2;" : "=f"(lo), "=f"(hi) : "l"(v));
}
__device__ __forceinline__ u64 relu2(u64 x) {
    float lo, hi; unpack2(x, lo, hi);
    lo = fmaxf(lo, 0.f); hi = fmaxf(hi, 0.f);
    u64 r; asm("mov.b64 %0, {%1, %2};" : "=l"(r) : "f"(lo), "f"(hi));
    return r;
}
// packed bf16x2: low half = a, high half = b
__device__ __forceinline__ u32 cvt_bf16x2(float a, float b) {
    u32 r; asm("cvt.rn.bf16x2.f32 %0, %1, %2;" : "=r"(r) : "f"(b), "f"(a));
    return r;
}
// hi/lo split of an fp32 pair (x,y) -> (hi u32, lo u32)
__device__ __forceinline__ void split2(float x, float y, u32& hi, u32& lo) {
    hi = cvt_bf16x2(x, y);
    float hx = __uint_as_float(hi << 16);
    float hy = __uint_as_float(hi & 0xFFFF0000u);
    lo = cvt_bf16x2(x - hx, y - hy);
}
__device__ __forceinline__ void mma16816(float& c0, float& c1, float& c2, float& c3,
                                         u32 a0, u32 a1, u32 a2, u32 a3,
                                         u32 b0, u32 b1) {
    asm volatile(
        "mma.sync.aligned.m16n8k16.row.col.f32.bf16.bf16.f32 "
        "{%0,%1,%2,%3}, {%4,%5,%6,%7}, {%8,%9}, {%0,%1,%2,%3};"
        : "+f"(c0), "+f"(c1), "+f"(c2), "+f"(c3)
        : "r"(a0), "r"(a1), "r"(a2), "r"(a3), "r"(b0), "r"(b1));
}

// -------------------- K_prep ------------------------------------------------
__global__ void __launch_bounds__(256) k_prep(const float* __restrict__ slots,
                                              const float* __restrict__ Wproj,
                                              const float* __restrict__ bproj) {
    int tid = threadIdx.x;
    if (blockIdx.x < 64) {
        __shared__ float ssh[8][D_MODEL];
        int b = blockIdx.x >> 3, ng = blockIdx.x & 7;
#pragma unroll
        for (int i = 0; i < 2; i++) {
            int q = i * 256 + tid;
            int row = q >> 6, c4 = q & 63;
            *(float4*)&ssh[row][c4 * 4] =
                *(const float4*)(slots + (b * NSLOT + ng * 8 + row) * D_MODEL + c4 * 4);
        }
        __syncthreads();
        int nl = tid >> 5, hq = tid & 31;
        const float* Ws = Wproj + D_MODEL * D_HID;
        float a0 = 0.f, a1 = 0.f, a2 = 0.f, a3 = 0.f;
#pragma unroll 8
        for (int k = 0; k < D_MODEL; k++) {
            float sv = ssh[nl][k];
            float4 wv = *(const float4*)(Ws + k * D_HID + hq * 4);
            a0 = fmaf(sv, wv.x, a0); a1 = fmaf(sv, wv.y, a1);
            a2 = fmaf(sv, wv.z, a2); a3 = fmaf(sv, wv.w, a3);
        }
        float4 bp = *(const float4*)(bproj + hq * 4);
        float4 o; o.x = a0 + bp.x; o.y = a1 + bp.y; o.z = a2 + bp.z; o.w = a3 + bp.w;
        *(float4*)(g_sproj + (b * NSLOT + ng * 8 + nl) * D_HID + hq * 4) = o;
    } else {
        __shared__ float tile[32][33];
        int bid = blockIdx.x - 64;
        int k0 = (bid & 7) * 32, h0 = (bid >> 3) * 32;
        int r = tid >> 5, c = tid & 31;
#pragma unroll
        for (int i = 0; i < 4; i++) {
            int row = i * 8 + r;
            tile[row][c] = Wproj[(k0 + row) * D_HID + h0 + c];
        }
        __syncthreads();
#pragma unroll
        for (int i = 0; i < 4; i++) {
            int row = i * 8 + r;
            float x = tile[c][row];
            __nv_bfloat16 hi = __float2bfloat16_rn(x);
            float lo = x - __bfloat162float(hi);
            g_Whi[(h0 + row) * D_MODEL + k0 + c] = hi;
            g_Wlo[(h0 + row) * D_MODEL + k0 + c] = __float2bfloat16_rn(lo);
        }
    }
}

// -------------------- K_gemm_mma --------------------------------------------
// grid 256: m0 = blk*32.  8 warps: mbase = (wid&1)*16, n0 = (wid>>1)*32.
// K chunked 64; B tile [128][BPAD] bf16 hi/lo in smem (pad -> conflict-free
// frag LDS.32).  A fragments straight from GMEM fp32, split to bf16 hi/lo.
#define BPAD 72

__global__ void __launch_bounds__(256) k_gemm_mma(const float* __restrict__ features) {
    __shared__ __align__(16) __nv_bfloat16 Bhi[128 * BPAD];   // 18 KB
    __shared__ __align__(16) __nv_bfloat16 Blo[128 * BPAD];   // 18 KB

    int tid = threadIdx.x, wid = tid >> 5, lane = tid & 31;
    int m0 = blockIdx.x * 32;
    int mbase = (wid & 1) * 16, n0 = (wid >> 1) * 32;

    int row_a = m0 + mbase + (lane >> 2);          // A frag row (and +8)
    int ca = (lane & 3) * 2;                       // A frag k-pair offset
    const float* arow = features + (size_t)row_a * D_MODEL + ca;

    float acc[4][4];
#pragma unroll
    for (int j = 0; j < 4; j++)
#pragma unroll
        for (int q = 0; q < 4; q++) acc[j][q] = 0.f;

#pragma unroll 1
    for (int kc = 0; kc < 4; kc++) {
        __syncthreads();
        // ---- stage B chunk: thread (n = tid>>1, half = tid&1) copies its
        //      FULL 32-bf16 slot (4x uint4) for both hi and lo tiles ----
        {
            int n = tid >> 1, half = tid & 1;
            const uint4* sh = (const uint4*)(g_Whi + n * D_MODEL + kc * 64 + half * 32);
            const uint4* sl = (const uint4*)(g_Wlo + n * D_MODEL + kc * 64 + half * 32);
            uint4* dh = (uint4*)(Bhi + n * BPAD + half * 32);
            uint4* dl = (uint4*)(Blo + n * BPAD + half * 32);
            dh[0] = sh[0]; dh[1] = sh[1]; dh[2] = sh[2]; dh[3] = sh[3];
            dl[0] = sl[0]; dl[1] = sl[1]; dl[2] = sl[2]; dl[3] = sl[3];
        }
        __syncthreads();

#pragma unroll
        for (int ks = 0; ks < 4; ks++) {
            int kk = kc * 64 + ks * 16;
            // ---- A fragments: direct LDG + hi/lo split ----
            float2 p00 = *(const float2*)(arow + kk);                    // a0
            float2 p10 = *(const float2*)(arow + kk + 8 * D_MODEL);      // a1
            float2 p01 = *(const float2*)(arow + kk + 8);                // a2
            float2 p11 = *(const float2*)(arow + kk + 8 * D_MODEL + 8);  // a3
            u32 ah[4], al[4];
            split2(p00.x, p00.y, ah[0], al[0]);
            split2(p10.x, p10.y, ah[1], al[1]);
            split2(p01.x, p01.y, ah[2], al[2]);
            split2(p11.x, p11.y, ah[3], al[3]);

#pragma unroll
            for (int j = 0; j < 4; j++) {
                int nrow = n0 + j * 8 + (lane >> 2);
                int kb = ks * 16 + (lane & 3) * 2;
                u32 bh0 = *(const u32*)(Bhi + nrow * BPAD + kb);
                u32 bh1 = *(const u32*)(Bhi + nrow * BPAD + kb + 8);
                u32 bl0 = *(const u32*)(Blo + nrow * BPAD + kb);
                u32 bl1 = *(const u32*)(Blo + nrow * BPAD + kb + 8);
                mma16816(acc[j][0], acc[j][1], acc[j][2], acc[j][3],
                         ah[0], ah[1], ah[2], ah[3], bh0, bh1);
                mma16816(acc[j][0], acc[j][1], acc[j][2], acc[j][3],
                         ah[0], ah[1], ah[2], ah[3], bl0, bl1);
                mma16816(acc[j][0], acc[j][1], acc[j][2], acc[j][3],
                         al[0], al[1], al[2], al[3], bh0, bh1);
            }
        }
    }

    // ---- epilogue: acc -> g_fproj (float2 stores) ----
    int r0 = m0 + mbase + (lane >> 2);
#pragma unroll
    for (int j = 0; j < 4; j++) {
        int col = n0 + j * 8 + (lane & 3) * 2;
        float2 v0; v0.x = acc[j][0]; v0.y = acc[j][1];
        float2 v1; v1.x = acc[j][2]; v1.y = acc[j][3];
        *(float2*)(g_fproj + (size_t)r0 * D_HID + col) = v0;
        *(float2*)(g_fproj + (size_t)(r0 + 8) * D_HID + col) = v1;
    }
}

// -------------------- K_out: relu-dot, 16-t tiles, grid 512 -----------------
#define FS 132
#define OUT_SMEM ((16 * FS + 64 * FS + 128) * 4)

__global__ void __launch_bounds__(256) k_out(const float* __restrict__ whead,
                                             const float* __restrict__ bhead,
                                             float* __restrict__ out) {
    extern __shared__ float osm[];
    float* fsh = osm;                 // 16 x 132
    float* ssh = osm + 16 * FS;       // 64 x 132
    u64*   wsh = (u64*)(osm + 16 * FS + 64 * FS);

    int tid = threadIdx.x, warp = tid >> 5, lane = tid & 31;
    int b = blockIdx.x >> 6, t0 = (blockIdx.x & 63) * 16;

#pragma unroll
    for (int i = 0; i < 2; i++) {     // fsh: 16 x 128
        int q = i * 256 + tid;
        int r = q >> 5, c4 = (q & 31) * 4;
        *(float4*)&fsh[r * FS + c4] =
            *(const float4*)(g_fproj + (size_t)(b * SEQ + t0 + r) * D_HID + c4);
    }
#pragma unroll
    for (int i = 0; i < 8; i++) {     // ssh: 64 x 128
        int q = i * 256 + tid;
        int r = q >> 5, c4 = (q & 31) * 4;
        *(float4*)&ssh[r * FS + c4] =
            *(const float4*)(g_sproj + (b * NSLOT + r) * D_HID + c4);
    }
    if (tid < 64) wsh[tid] = ((const u64*)whead)[tid];
    float bh = bhead[0];
    __syncthreads();

    int tq = lane >> 2, np = lane & 3;
    int n0 = warp * 8 + np * 2;
    const float* fp = fsh + tq * FS;
    const float* sp = ssh + n0 * FS;

    u64 bacc[2][2];
    bacc[0][0] = bacc[0][1] = bacc[1][0] = bacc[1][1] = 0ULL;

#pragma unroll 4
    for (int hp = 0; hp < 64; hp++) {
        u64 w2 = wsh[hp];
        u64 s20 = *(const u64*)&sp[2 * hp];
        u64 s21 = *(const u64*)&sp[FS + 2 * hp];
#pragma unroll
        for (int i = 0; i < 2; i++) {
            u64 f2 = *(const u64*)&fp[i * 8 * FS + 2 * hp];
            bacc[i][0] = fma2(relu2(add2(f2, s20)), w2, bacc[i][0]);
            bacc[i][1] = fma2(relu2(add2(f2, s21)), w2, bacc[i][1]);
        }
    }

#pragma unroll
    for (int i = 0; i < 2; i++) {
        int t = tq + 8 * i;
        float a, c, d, e;
        unpack2(bacc[i][0], a, c);
        unpack2(bacc[i][1], d, e);
        float2 o; o.x = a + c + bh; o.y = d + e + bh;
        *(float2*)&out[(size_t)(b * SEQ + t0 + t) * NSLOT + n0] = o;
    }
}

// -------------------- launch -----------------------------------------------
extern "C" void kernel_launch(void* const* d_in, const int* in_sizes, int n_in,
                              void* d_out, int out_size) {
    const float* features = (const float*)d_in[0];
    const float* slots    = (const float*)d_in[1];
    const float* W_proj   = (const float*)d_in[2];
    const float* b_proj   = (const float*)d_in[3];
    const float* w_head   = (const float*)d_in[4];
    const float* b_head   = (const float*)d_in[5];
    float* out = (float*)d_out;

    cudaFuncSetAttribute(k_out, cudaFuncAttributeMaxDynamicSharedMemorySize,
                         OUT_SMEM);

    k_prep<<<96, 256>>>(slots, W_proj, b_proj);
    k_gemm_mma<<<MROWS / 32, 256>>>(features);
    k_out<<<512, 256, OUT_SMEM>>>(w_head, b_head, out);
}

// round 10
// speedup vs baseline: 1.7250x; 1.4760x over previous
#include <cuda_runtime.h>
#include <cuda_bf16.h>
#include <cstdint>

// ---------------------------------------------------------------------------
// ASDHead v7 — unified HMMA GEMM for f_proj AND s_proj:
//  k_trans    : W_proj[512][128] -> g_Whi/g_Wlo [h][k] bf16 hi/lo, grid 64
//  k_gemm_mma : blocks 0..255  : f_proj = features @ W_f      (koff=0)
//               blocks 256..271: s_proj = slots @ W_s + bproj (koff=256)
//               mma.sync m16n8k16 bf16, 3-product hi/lo split, fp32 accum
//  k_out      : out = sum_h relu(f+s)*w + b. 16-t tiles, grid 512.
// Rationale: R9 ncu showed old k_prep at 41.6us / issue 4.2% (MLP~1 sproj
// loop). sproj is the same GEMM shape -> fold into the tensor kernel.
// ---------------------------------------------------------------------------

#define D_MODEL 256
#define D_HID   128
#define BATCH   8
#define SEQ     1024
#define NSLOT   64
#define MROWS   (BATCH * SEQ)
#define WK      512                      // full W^T k-extent (W_f | W_s)

typedef unsigned long long u64;
typedef unsigned int u32;

__device__ float g_sproj[BATCH * NSLOT * D_HID];              // 256 KB
__device__ __align__(16) __nv_bfloat16 g_Whi[D_HID * WK];     // W^T hi [h][512]
__device__ __align__(16) __nv_bfloat16 g_Wlo[D_HID * WK];     // W^T lo [h][512]
__device__ float g_fproj[MROWS * D_HID];                      // 4 MB

// -------------------- helpers ----------------------------------------------
__device__ __forceinline__ u64 fma2(u64 a, u64 b, u64 c) {
    u64 d; asm("fma.rn.f32x2 %0, %1, %2, %3;" : "=l"(d) : "l"(a), "l"(b), "l"(c));
    return d;
}
__device__ __forceinline__ u64 add2(u64 a, u64 b) {
    u64 d; asm("add.rn.f32x2 %0, %1, %2;" : "=l"(d) : "l"(a), "l"(b));
    return d;
}
__device__ __forceinline__ void unpack2(u64 v, float& lo, float& hi) {
    asm("mov.b64 {%0, %1}, %2;" : "=f"(lo), "=f"(hi) : "l"(v));
}
__device__ __forceinline__ u64 relu2(u64 x) {
    float lo, hi; unpack2(x, lo, hi);
    lo = fmaxf(lo, 0.f); hi = fmaxf(hi, 0.f);
    u64 r; asm("mov.b64 %0, {%1, %2};" : "=l"(r) : "f"(lo), "f"(hi));
    return r;
}
__device__ __forceinline__ u32 cvt_bf16x2(float a, float b) {
    u32 r; asm("cvt.rn.bf16x2.f32 %0, %1, %2;" : "=r"(r) : "f"(b), "f"(a));
    return r;
}
__device__ __forceinline__ void split2(float x, float y, u32& hi, u32& lo) {
    hi = cvt_bf16x2(x, y);
    float hx = __uint_as_float(hi << 16);
    float hy = __uint_as_float(hi & 0xFFFF0000u);
    lo = cvt_bf16x2(x - hx, y - hy);
}
__device__ __forceinline__ void mma16816(float& c0, float& c1, float& c2, float& c3,
                                         u32 a0, u32 a1, u32 a2, u32 a3,
                                         u32 b0, u32 b1) {
    asm volatile(
        "mma.sync.aligned.m16n8k16.row.col.f32.bf16.bf16.f32 "
        "{%0,%1,%2,%3}, {%4,%5,%6,%7}, {%8,%9}, {%0,%1,%2,%3};"
        : "+f"(c0), "+f"(c1), "+f"(c2), "+f"(c3)
        : "r"(a0), "r"(a1), "r"(a2), "r"(a3), "r"(b0), "r"(b1));
}

// -------------------- K_trans: W_proj -> W^T bf16 hi/lo ---------------------
// grid (16,4): 32x32 tiles. tile rows = k (512), cols = h (128).
__global__ void __launch_bounds__(256) k_trans(const float* __restrict__ Wproj) {
    __shared__ float tile[32][33];
    int k0 = blockIdx.x * 32, h0 = blockIdx.y * 32;
    int r = threadIdx.x >> 5, c = threadIdx.x & 31;
#pragma unroll
    for (int i = 0; i < 4; i++) {
        int row = i * 8 + r;
        tile[row][c] = Wproj[(k0 + row) * D_HID + h0 + c];
    }
    __syncthreads();
#pragma unroll
    for (int i = 0; i < 4; i++) {
        int row = i * 8 + r;                    // h-local
        float x = tile[c][row];                 // = Wproj[k0+c][h0+row]
        __nv_bfloat16 hi = __float2bfloat16_rn(x);
        float lo = x - __bfloat162float(hi);
        g_Whi[(h0 + row) * WK + k0 + c] = hi;
        g_Wlo[(h0 + row) * WK + k0 + c] = __float2bfloat16_rn(lo);
    }
}

// -------------------- K_gemm_mma --------------------------------------------
// grid 272.  Blocks 0..255: features GEMM (koff 0, out g_fproj).
//            Blocks 256..271: slots GEMM (koff 256, +bproj, out g_sproj).
// 8 warps: mbase = (wid&1)*16, n0 = (wid>>1)*32.  K chunked 64.
// B tile [128][BPAD] bf16 hi/lo in smem; A frags direct from GMEM fp32.
#define BPAD 72

__global__ void __launch_bounds__(256) k_gemm_mma(const float* __restrict__ features,
                                                  const float* __restrict__ slots,
                                                  const float* __restrict__ bproj) {
    __shared__ __align__(16) __nv_bfloat16 Bhi[128 * BPAD];   // 18 KB
    __shared__ __align__(16) __nv_bfloat16 Blo[128 * BPAD];   // 18 KB

    int tid = threadIdx.x, wid = tid >> 5, lane = tid & 31;
    bool is_slot = blockIdx.x >= 256;
    int m0   = is_slot ? (blockIdx.x - 256) * 32 : blockIdx.x * 32;
    int koff = is_slot ? 256 : 0;
    const float* Abase = is_slot ? slots : features;
    float* Obase = is_slot ? g_sproj : g_fproj;

    int mbase = (wid & 1) * 16, n0 = (wid >> 1) * 32;
    int row_a = m0 + mbase + (lane >> 2);
    int ca = (lane & 3) * 2;
    const float* arow = Abase + (size_t)row_a * D_MODEL + ca;

    float acc[4][4];
#pragma unroll
    for (int j = 0; j < 4; j++)
#pragma unroll
        for (int q = 0; q < 4; q++) acc[j][q] = 0.f;

#pragma unroll 1
    for (int kc = 0; kc < 4; kc++) {
        __syncthreads();
        // stage B chunk: thread (n = tid>>1, half = tid&1) copies its full
        // 32-bf16 slot (4x uint4) for hi and lo tiles.
        {
            int n = tid >> 1, half = tid & 1;
            const uint4* sh = (const uint4*)(g_Whi + n * WK + koff + kc * 64 + half * 32);
            const uint4* sl = (const uint4*)(g_Wlo + n * WK + koff + kc * 64 + half * 32);
            uint4* dh = (uint4*)(Bhi + n * BPAD + half * 32);
            uint4* dl = (uint4*)(Blo + n * BPAD + half * 32);
            dh[0] = sh[0]; dh[1] = sh[1]; dh[2] = sh[2]; dh[3] = sh[3];
            dl[0] = sl[0]; dl[1] = sl[1]; dl[2] = sl[2]; dl[3] = sl[3];
        }
        __syncthreads();

#pragma unroll
        for (int ks = 0; ks < 4; ks++) {
            int kk = kc * 64 + ks * 16;
            float2 p00 = *(const float2*)(arow + kk);
            float2 p10 = *(const float2*)(arow + kk + 8 * D_MODEL);
            float2 p01 = *(const float2*)(arow + kk + 8);
            float2 p11 = *(const float2*)(arow + kk + 8 * D_MODEL + 8);
            u32 ah[4], al[4];
            split2(p00.x, p00.y, ah[0], al[0]);
            split2(p10.x, p10.y, ah[1], al[1]);
            split2(p01.x, p01.y, ah[2], al[2]);
            split2(p11.x, p11.y, ah[3], al[3]);

#pragma unroll
            for (int j = 0; j < 4; j++) {
                int nrow = n0 + j * 8 + (lane >> 2);
                int kb = ks * 16 + (lane & 3) * 2;
                u32 bh0 = *(const u32*)(Bhi + nrow * BPAD + kb);
                u32 bh1 = *(const u32*)(Bhi + nrow * BPAD + kb + 8);
                u32 bl0 = *(const u32*)(Blo + nrow * BPAD + kb);
                u32 bl1 = *(const u32*)(Blo + nrow * BPAD + kb + 8);
                mma16816(acc[j][0], acc[j][1], acc[j][2], acc[j][3],
                         ah[0], ah[1], ah[2], ah[3], bh0, bh1);
                mma16816(acc[j][0], acc[j][1], acc[j][2], acc[j][3],
                         ah[0], ah[1], ah[2], ah[3], bl0, bl1);
                mma16816(acc[j][0], acc[j][1], acc[j][2], acc[j][3],
                         al[0], al[1], al[2], al[3], bh0, bh1);
            }
        }
    }

    // epilogue: acc -> Obase (+ bproj for slot blocks)
    int r0 = m0 + mbase + (lane >> 2);
#pragma unroll
    for (int j = 0; j < 4; j++) {
        int col = n0 + j * 8 + (lane & 3) * 2;
        float2 bp = make_float2(0.f, 0.f);
        if (is_slot) bp = *(const float2*)(bproj + col);
        float2 v0; v0.x = acc[j][0] + bp.x; v0.y = acc[j][1] + bp.y;
        float2 v1; v1.x = acc[j][2] + bp.x; v1.y = acc[j][3] + bp.y;
        *(float2*)(Obase + (size_t)r0 * D_HID + col) = v0;
        *(float2*)(Obase + (size_t)(r0 + 8) * D_HID + col) = v1;
    }
}

// -------------------- K_out: relu-dot, 16-t tiles, grid 512 -----------------
#define FS 132
#define OUT_SMEM ((16 * FS + 64 * FS + 128) * 4)

__global__ void __launch_bounds__(256) k_out(const float* __restrict__ whead,
                                             const float* __restrict__ bhead,
                                             float* __restrict__ out) {
    extern __shared__ float osm[];
    float* fsh = osm;                 // 16 x 132
    float* ssh = osm + 16 * FS;       // 64 x 132
    u64*   wsh = (u64*)(osm + 16 * FS + 64 * FS);

    int tid = threadIdx.x, warp = tid >> 5, lane = tid & 31;
    int b = blockIdx.x >> 6, t0 = (blockIdx.x & 63) * 16;

#pragma unroll
    for (int i = 0; i < 2; i++) {
        int q = i * 256 + tid;
        int r = q >> 5, c4 = (q & 31) * 4;
        *(float4*)&fsh[r * FS + c4] =
            *(const float4*)(g_fproj + (size_t)(b * SEQ + t0 + r) * D_HID + c4);
    }
#pragma unroll
    for (int i = 0; i < 8; i++) {
        int q = i * 256 + tid;
        int r = q >> 5, c4 = (q & 31) * 4;
        *(float4*)&ssh[r * FS + c4] =
            *(const float4*)(g_sproj + (b * NSLOT + r) * D_HID + c4);
    }
    if (tid < 64) wsh[tid] = ((const u64*)whead)[tid];
    float bh = bhead[0];
    __syncthreads();

    int tq = lane >> 2, np = lane & 3;
    int n0 = warp * 8 + np * 2;
    const float* fp = fsh + tq * FS;
    const float* sp = ssh + n0 * FS;

    u64 bacc[2][2];
    bacc[0][0] = bacc[0][1] = bacc[1][0] = bacc[1][1] = 0ULL;

#pragma unroll 4
    for (int hp = 0; hp < 64; hp++) {
        u64 w2 = wsh[hp];
        u64 s20 = *(const u64*)&sp[2 * hp];
        u64 s21 = *(const u64*)&sp[FS + 2 * hp];
#pragma unroll
        for (int i = 0; i < 2; i++) {
            u64 f2 = *(const u64*)&fp[i * 8 * FS + 2 * hp];
            bacc[i][0] = fma2(relu2(add2(f2, s20)), w2, bacc[i][0]);
            bacc[i][1] = fma2(relu2(add2(f2, s21)), w2, bacc[i][1]);
        }
    }

#pragma unroll
    for (int i = 0; i < 2; i++) {
        int t = tq + 8 * i;
        float a, c, d, e;
        unpack2(bacc[i][0], a, c);
        unpack2(bacc[i][1], d, e);
        float2 o; o.x = a + c + bh; o.y = d + e + bh;
        *(float2*)&out[(size_t)(b * SEQ + t0 + t) * NSLOT + n0] = o;
    }
}

// -------------------- launch -----------------------------------------------
extern "C" void kernel_launch(void* const* d_in, const int* in_sizes, int n_in,
                              void* d_out, int out_size) {
    const float* features = (const float*)d_in[0];
    const float* slots    = (const float*)d_in[1];
    const float* W_proj   = (const float*)d_in[2];
    const float* b_proj   = (const float*)d_in[3];
    const float* w_head   = (const float*)d_in[4];
    const float* b_head   = (const float*)d_in[5];
    float* out = (float*)d_out;

    cudaFuncSetAttribute(k_out, cudaFuncAttributeMaxDynamicSharedMemorySize,
                         OUT_SMEM);

    k_trans<<<dim3(16, 4), 256>>>(W_proj);
    k_gemm_mma<<<272, 256>>>(features, slots, b_proj);
    k_out<<<512, 256, OUT_SMEM>>>(w_head, b_head, out);
}